// round 6
// baseline (speedup 1.0000x reference)
#include <cuda_runtime.h>
#include <cstdint>

#define BB 32
#define NN 128
#define NIN 16
#define MHID 64
#define MOUT 64
#define NHID 64
#define NOUT 16
#define KT 4
#define EDGES (NN * (NN - 1))

// Scratch (no cudaMalloc allowed)
__device__ float g_U[BB * NN * KT * MHID];   // [b][n][k][h] sender proj
__device__ float g_V[BB * NN * KT * MHID];   // [b][n][k][h] receiver proj + b1
__device__ float g_W2T[KT * MOUT * MHID];    // W2 transposed [k][m][kk], tf32-rounded
__device__ float g_AGG[BB * NN * MOUT];      // aggregated messages per node

// ---------------- helpers ----------------
__device__ __forceinline__ uint32_t smem_u32(const void* p) {
    uint32_t a;
    asm("{ .reg .u64 t; cvta.to.shared.u64 t, %1; cvt.u32.u64 %0, t; }" : "=r"(a) : "l"(p));
    return a;
}
__device__ __forceinline__ uint32_t f2tf32(float x) {
    uint32_t r; asm("cvt.rna.tf32.f32 %0, %1;" : "=r"(r) : "f"(x)); return r;
}

#if defined(__CUDA_ARCH_FEAT_SM103_ALL)
__device__ __forceinline__ void mma_tf32_ss(uint32_t d, uint64_t a, uint64_t b,
                                            uint32_t idesc, uint32_t en) {
    asm volatile(
        "{\n\t.reg .pred p;\n\tsetp.ne.u32 p, %4, 0;\n\t"
        "tcgen05.mma.cta_group::1.kind::tf32 [%0], %1, %2, %3, {%5, %5, %5, %5}, p;\n\t}\n"
        :: "r"(d), "l"(a), "l"(b), "r"(idesc), "r"(en), "r"(0u) : "memory");
}
#define MBAR_WAIT_PARITY(addr, ph) do {                                          \
    uint32_t _m = (addr), _p = (ph), _done;                                      \
    asm volatile("{\n\t.reg .pred p;\n\t"                                        \
        "mbarrier.try_wait.parity.acquire.cta.shared::cta.b64 p, [%1], %2;\n\t"  \
        "selp.b32 %0, 1, 0, p;\n\t}" : "=r"(_done) : "r"(_m), "r"(_p) : "memory");\
    if (!_done) {                                                                \
        asm volatile("{\n\t.reg .pred P1;\n\t"                                   \
            "WL_%=:\n\t"                                                         \
            "mbarrier.try_wait.parity.acquire.cta.shared::cta.b64 P1, [%0], %1, 0x989680;\n\t" \
            "@P1 bra.uni WD_%=;\n\tbra.uni WL_%=;\n\tWD_%=:\n\t}"                \
            :: "r"(_m), "r"(_p) : "memory");                                     \
    } } while (0)
#define LDTM_X16(r, addr)                                                        \
    asm volatile("tcgen05.ld.sync.aligned.32x32b.x16.b32 "                       \
        "{%0, %1, %2, %3, %4, %5, %6, %7, %8, %9, %10, %11, %12, %13, %14, %15}, [%16];" \
        : "=r"((r)[0]),  "=r"((r)[1]),  "=r"((r)[2]),  "=r"((r)[3]),             \
          "=r"((r)[4]),  "=r"((r)[5]),  "=r"((r)[6]),  "=r"((r)[7]),             \
          "=r"((r)[8]),  "=r"((r)[9]),  "=r"((r)[10]), "=r"((r)[11]),            \
          "=r"((r)[12]), "=r"((r)[13]), "=r"((r)[14]), "=r"((r)[15])             \
        : "r"(addr))
#define IDESC_TF32 0x08100910u
#define DESC_BASE ((2ull << 61) | (1ull << 46) | (64ull << 32) | (1ull << 16))
__device__ __forceinline__ uint64_t mk_desc(uint32_t addr) {
    return DESC_BASE | ((uint64_t)(addr >> 4) & 0x3FFF);
}
#endif

// decoder dynamic smem layout (from 1024-aligned base)
#define OFF_B     0          // 4 x 16384 = 65536 (W2T, SW128)
#define OFF_A     65536      // 4 x 32768 = 131072 (h1 tiles, SW128)
#define DEC_DYN   (65536 + 131072 + 1024)

// node-MLP kernel smem (floats)
#define NOFF_W1   0            // 80*64
#define NOFF_W2   5120         // 64*64
#define NOFF_W3   9216         // 64*16
#define NOFF_B    10240        // 144
#define NOFF_AUG  10384        // 16*80
#define NOFF_H1   11664        // 16*64
#define NOFF_H2   12688        // 16*64
#define NODE_DYN  ((12688 + 1024 + 64) * 4)

// ---------------------------------------------------------------------------
__global__ void w2t_kernel(const float* __restrict__ W2) {
    int idx = blockIdx.x * 256 + threadIdx.x;
    if (idx < KT * MOUT * MHID) {
        int k = idx >> 12, rem = idx & 4095, kk = rem >> 6, m = rem & 63;
        uint32_t v = f2tf32(W2[(k * MHID + kk) * MOUT + m]);
        ((uint32_t*)g_W2T)[(k * MOUT + m) * MHID + kk] = v;
    }
}

// ---------------------------------------------------------------------------
// uv: grid (8, BB), 256 threads, 16 nodes per CTA; W1 in registers.
// ---------------------------------------------------------------------------
__global__ __launch_bounds__(256) void uv_kernel(
    const float* __restrict__ inp, const float* __restrict__ W1,
    const float* __restrict__ b1)
{
    const int g = blockIdx.x, b = blockIdx.y;
    const int n0 = g * 16;
    const int t = threadIdx.x;
    const int k = t >> 6, h = t & 63;

    __shared__ float xs[16][NIN];
    {
        const int nn = t & 15, f = t >> 4;
        xs[nn][f] = inp[(b * NIN + f) * NN + n0 + nn];
    }
    __syncthreads();

    const float* w = W1 + k * (2 * NIN) * MHID;
    const float bv = b1[k * MHID + h];
    float u[16], v[16];
#pragma unroll
    for (int nn = 0; nn < 16; nn++) { u[nn] = 0.f; v[nn] = bv; }
#pragma unroll
    for (int f = 0; f < NIN; f++) {
        const float wu = w[f * MHID + h];
        const float wv = w[(NIN + f) * MHID + h];
#pragma unroll
        for (int nn = 0; nn < 16; nn++) {
            u[nn] = fmaf(xs[nn][f], wu, u[nn]);
            v[nn] = fmaf(xs[nn][f], wv, v[nn]);
        }
    }
#pragma unroll
    for (int nn = 0; nn < 16; nn++) {
        g_U[((b * NN + n0 + nn) * KT + k) * MHID + h] = u[nn];
        g_V[((b * NN + n0 + nn) * KT + k) * MHID + h] = v[nn];
    }
}

// ---------------------------------------------------------------------------
// Persistent warp-specialized decoder: grid 148, 512 threads.
//   warps 0-11  : A-build + MMA issue
//   warps 12-15 : TMEM epilogue + aggregation
// ---------------------------------------------------------------------------
__global__ __launch_bounds__(512, 1) void decoder_kernel(
    const float* __restrict__ rel_types, const float* __restrict__ W2,
    const float* __restrict__ b2)
{
    extern __shared__ char dsm[];
    __shared__ __align__(16) float vs[KT][MHID];
    __shared__ float b2s[KT][MOUT];
    __shared__ float part[4][MOUT];
    __shared__ uint32_t tmem_ptr_s;
    __shared__ __align__(8) uint64_t mbar[3];   // [0]=mma done, [1..2]=bank free

    const int t = threadIdx.x;
    const int wid = t >> 5, lane = t & 31;

    const uint32_t dyn = smem_u32(dsm);
    const uint32_t base = (dyn + 1023) & ~1023u;
    char* P = dsm + (base - dyn);

    if (t < 256) b2s[t >> 6][t & 63] = b2[t];

#if defined(__CUDA_ARCH_FEAT_SM103_ALL)
    const uint32_t mb_mma  = smem_u32(&mbar[0]);
    const uint32_t mb_free0 = smem_u32(&mbar[1]);
    const uint32_t mb_free1 = smem_u32(&mbar[2]);

    // stage all 4 B tiles (W2T, SW128) once
    for (int idx = t; idx < KT * 64 * 16; idx += 512) {
        const int k = idx >> 10, n = (idx >> 4) & 63, c = (idx & 15) * 4;
        uint4 w4 = *(const uint4*)((const uint32_t*)g_W2T + (k * MOUT + n) * MHID + c);
        uint32_t byte = ((n >> 3) + (c >> 5) * 8) * 1024 + (n & 7) * 128 + (c & 31) * 4;
        byte ^= (byte >> 3) & 0x70;
        *(uint4*)(P + OFF_B + k * 16384 + byte) = w4;
    }
    if (t == 0) {
        asm volatile("mbarrier.init.shared.b64 [%0], 1;" :: "r"(mb_mma) : "memory");
        asm volatile("mbarrier.init.shared.b64 [%0], 1;" :: "r"(mb_free0) : "memory");
        asm volatile("mbarrier.init.shared.b64 [%0], 1;" :: "r"(mb_free1) : "memory");
    }
    if (wid == 0) {
        asm volatile("tcgen05.alloc.cta_group::1.sync.aligned.shared::cta.b32 [%0], %1;"
                     :: "r"(smem_u32(&tmem_ptr_s)), "r"(512u) : "memory");
        asm volatile("tcgen05.relinquish_alloc_permit.cta_group::1.sync.aligned;");
    }
    __syncthreads();
    const uint32_t tmem = tmem_ptr_s;

    if (wid < 12) {
        // ===================== PRODUCER =====================
        int pmP = 0, phF0 = 0, phF1 = 0, tc = 0;
        for (int tile = blockIdx.x; tile < BB * NN; tile += gridDim.x, tc++) {
            const int b = tile >> 7, i = tile & 127;
            const int q = tc & 1;

            if (tc > 0) { MBAR_WAIT_PARITY(mb_mma, pmP); pmP ^= 1; }  // A free
            if (t < 256) vs[t >> 6][t & 63] = g_V[((b * NN + i) * KT) * MHID + t];
            asm volatile("bar.sync 1, 384;" ::: "memory");

            // build all 4 A tiles
            for (int idx = t; idx < 128 * KT * 16; idx += 384) {
                const int r = idx >> 6, k = (idx >> 4) & 3, c = (idx & 15) * 4;
                uint4 w4 = make_uint4(0u, 0u, 0u, 0u);
                if (r < NN - 1) {
                    const int j = r + (r >= i);
                    const float4 u = *(const float4*)(g_U + ((b * NN + j) * KT + k) * MHID + c);
                    const float4 vv = *(const float4*)&vs[k][c];
                    w4.x = f2tf32(fmaxf(u.x + vv.x, 0.f));
                    w4.y = f2tf32(fmaxf(u.y + vv.y, 0.f));
                    w4.z = f2tf32(fmaxf(u.z + vv.z, 0.f));
                    w4.w = f2tf32(fmaxf(u.w + vv.w, 0.f));
                }
                uint32_t byte = ((r >> 3) + (c >> 5) * 16) * 1024 + (r & 7) * 128 + (c & 31) * 4;
                byte ^= (byte >> 3) & 0x70;
                *(uint4*)(P + OFF_A + k * 32768 + byte) = w4;
            }
            asm volatile("bar.sync 1, 384;" ::: "memory");

            if (t == 0) {
                // TMEM bank-set q must be free (epilogue of tile tc-2 done)
                if (tc >= 2) {
                    if (q == 0) { MBAR_WAIT_PARITY(mb_free0, phF0); phF0 ^= 1; }
                    else        { MBAR_WAIT_PARITY(mb_free1, phF1); phF1 ^= 1; }
                }
                asm volatile("fence.proxy.async.shared::cta;" ::: "memory");
#pragma unroll
                for (int k = 0; k < KT; k++) {
                    const uint64_t ad = mk_desc(base + OFF_A + k * 32768);
                    const uint64_t bd = mk_desc(base + OFF_B + k * 16384);
                    const uint32_t dcol = tmem + (q * 4 + k) * 64;
#pragma unroll
                    for (int s = 0; s < 8; s++)
                        mma_tf32_ss(dcol,
                                    ad + ((s >> 2) ? 1024u : 0u) + (s & 3) * 2,
                                    bd + ((s >> 2) ? 512u : 0u) + (s & 3) * 2,
                                    IDESC_TF32, (uint32_t)(s > 0));
                }
                asm volatile(
                    "tcgen05.commit.cta_group::1.mbarrier::arrive::one.shared::cluster.b64 [%0];"
                    :: "r"(mb_mma) : "memory");
            }
        }
    } else {
        // ===================== EPILOGUE =====================
        const int ewid = wid - 12;             // 0..3 = TMEM subpartition
        const int jrow = ewid * 32 + lane;     // 0..127
        int pmE = 0, tc = 0;
        for (int tile = blockIdx.x; tile < BB * NN; tile += gridDim.x, tc++) {
            const int b = tile >> 7, i = tile & 127;
            const int qe = tc & 1;

            float4 rt = make_float4(0.f, 0.f, 0.f, 0.f);
            if (jrow < NN - 1)
                rt = *(const float4*)(rel_types +
                        ((size_t)b * EDGES + (size_t)i * (NN - 1) + jrow) * KT);

            MBAR_WAIT_PARITY(mb_mma, pmE); pmE ^= 1;   // MMA(tc) done
            asm volatile("tcgen05.fence::after_thread_sync;" ::: "memory");

            float acc[64];
#pragma unroll
            for (int c = 0; c < 64; c++) acc[c] = 0.f;
#pragma unroll
            for (int k = 0; k < KT; k++) {
                const float rtk = (k == 0) ? rt.x : (k == 1) ? rt.y : (k == 2) ? rt.z : rt.w;
#pragma unroll
                for (int ch = 0; ch < 4; ch++) {
                    uint32_t d[16];
                    LDTM_X16(d, tmem + (qe * 4 + k) * 64 + ch * 16);
                    asm volatile("tcgen05.wait::ld.sync.aligned;" ::: "memory");
#pragma unroll
                    for (int c = 0; c < 16; c++) {
                        const float val =
                            fmaxf(__uint_as_float(d[c]) + b2s[k][ch * 16 + c], 0.f);
                        acc[ch * 16 + c] = fmaf(rtk, val, acc[ch * 16 + c]);
                    }
                }
            }
            asm volatile("tcgen05.fence::before_thread_sync;" ::: "memory");

            // butterfly-split reduction: lane ends with cols {2*lane, 2*lane+1}
#pragma unroll
            for (int o = 16, half = 32; o >= 1; o >>= 1, half >>= 1) {
                const bool up = (lane & o) != 0;
#pragma unroll
                for (int c = 0; c < 32; c++) {
                    if (c >= half) break;
                    const float send = up ? acc[c] : acc[c + half];
                    const float recv = __shfl_xor_sync(0xFFFFFFFFu, send, o);
                    acc[c] = (up ? acc[c + half] : acc[c]) + recv;
                }
            }
            part[ewid][2 * lane] = acc[0];
            part[ewid][2 * lane + 1] = acc[1];
            asm volatile("bar.sync 2, 128;" ::: "memory");
            if (t == 384) {   // signal TMEM bank-set free
                if (qe == 0)
                    asm volatile("mbarrier.arrive.shared.b64 _, [%0];" :: "r"(mb_free0) : "memory");
                else
                    asm volatile("mbarrier.arrive.shared.b64 _, [%0];" :: "r"(mb_free1) : "memory");
            }
            {
                const int idx = t - 384;
                if (idx < 64)
                    g_AGG[(b * NN + i) * MOUT + idx] =
                        part[0][idx] + part[1][idx] + part[2][idx] + part[3][idx];
            }
            asm volatile("bar.sync 2, 128;" ::: "memory");
        }
    }

    __syncthreads();
    if (t == 0) {
        asm volatile("mbarrier.inval.shared.b64 [%0];" :: "r"(mb_mma) : "memory");
        asm volatile("mbarrier.inval.shared.b64 [%0];" :: "r"(mb_free0) : "memory");
        asm volatile("mbarrier.inval.shared.b64 [%0];" :: "r"(mb_free1) : "memory");
    }
    if (wid == 0)
        asm volatile("tcgen05.dealloc.cta_group::1.sync.aligned.b32 %0, %1;"
                     :: "r"(tmem), "r"(512u));
#else
    // ============ SIMT fallback (compile-only for plain sm_103) ============
    __shared__ float rts0[NN][KT];
    float* h1  = (float*)P;                  // [128][68]
    float* W2s = (float*)(P + 128 * 68 * 4); // [64][64]

    for (int tile = blockIdx.x; tile < BB * NN; tile += gridDim.x) {
        const int b = tile >> 7, i = tile & 127;
        __syncthreads();
        if (t < 256) vs[t >> 6][t & 63] = g_V[((b * NN + i) * KT) * MHID + t];
        {
            const float* rtp = rel_types + (size_t)(b * EDGES + i * (NN - 1)) * KT;
            for (int idx = t; idx < (NN - 1) * KT; idx += 512)
                rts0[idx >> 2][idx & 3] = rtp[idx];
            if (t < KT) rts0[NN - 1][t] = 0.f;
        }
        const int r = t >> 2, cq = (t & 3) * 16;
        float aggv[16];
#pragma unroll
        for (int c = 0; c < 16; c++) aggv[c] = 0.f;
        for (int k = 0; k < KT; k++) {
            __syncthreads();
            for (int idx = t; idx < 128 * 64; idx += 512) {
                const int rr = idx >> 6, h = idx & 63;
                float val = 0.f;
                if (rr < NN - 1) {
                    const int j = rr + (rr >= i);
                    val = fmaxf(g_U[((b * NN + j) * KT + k) * MHID + h] + vs[k][h], 0.f);
                }
                h1[rr * 68 + h] = val;
            }
            for (int idx = t; idx < 64 * 64; idx += 512)
                W2s[idx] = W2[k * 64 * 64 + idx];
            __syncthreads();
            float acc[16];
#pragma unroll
            for (int c = 0; c < 16; c++) acc[c] = 0.f;
            for (int kk = 0; kk < 64; kk++) {
                const float a = h1[r * 68 + kk];
#pragma unroll
                for (int c = 0; c < 16; c++)
                    acc[c] = fmaf(a, W2s[kk * 64 + cq + c], acc[c]);
            }
            const float rt = rts0[r][k];
#pragma unroll
            for (int c = 0; c < 16; c++)
                aggv[c] = fmaf(rt, fmaxf(acc[c] + b2s[k][cq + c], 0.f), aggv[c]);
        }
        __syncthreads();
        float* red = (float*)P;
#pragma unroll
        for (int c = 0; c < 16; c++) red[(cq + c) * 132 + r] = aggv[c];
        __syncthreads();
        if (t < 64) {
            float s = 0.f;
            for (int l = 0; l < 128; l++) s += red[t * 132 + l];
            g_AGG[(b * NN + i) * MOUT + t] = s;
        }
        __syncthreads();
    }
#endif
}

// ---------------------------------------------------------------------------
// Node MLP: grid 256 (16 nodes per CTA), 256 threads.
// ---------------------------------------------------------------------------
__global__ __launch_bounds__(256) void node_kernel(
    const float* __restrict__ inp,
    const float* __restrict__ Wo1, const float* __restrict__ bo1,
    const float* __restrict__ Wo2, const float* __restrict__ bo2,
    const float* __restrict__ Wo3, const float* __restrict__ bo3,
    float* __restrict__ out)
{
    extern __shared__ float nsm[];
    float* sW1 = nsm + NOFF_W1;
    float* sW2 = nsm + NOFF_W2;
    float* sW3 = nsm + NOFF_W3;
    float* sB  = nsm + NOFF_B;
    float* aug = nsm + NOFF_AUG;   // [16][80]
    float* h1  = nsm + NOFF_H1;    // [16][64]
    float* h2  = nsm + NOFF_H2;    // [16][64]

    const int t = threadIdx.x;
    const int b = blockIdx.x >> 3, n0 = (blockIdx.x & 7) * 16;

    for (int idx = t; idx < 80 * 64; idx += 256) sW1[idx] = Wo1[idx];
    for (int idx = t; idx < 64 * 64; idx += 256) sW2[idx] = Wo2[idx];
    for (int idx = t; idx < 64 * 16; idx += 256) sW3[idx] = Wo3[idx];
    if (t < 64) sB[t] = bo1[t];
    if (t < 64) sB[64 + t] = bo2[t];
    if (t < 16) sB[128 + t] = bo3[t];

    for (int idx = t; idx < 16 * 80; idx += 256) {
        const int nn = idx / 80, f = idx % 80;
        aug[nn * 80 + f] = (f < NIN)
            ? inp[(b * NIN + f) * NN + (n0 + nn)]
            : g_AGG[(b * NN + n0 + nn) * MOUT + (f - NIN)];
    }
    __syncthreads();

    const int nn = t >> 4, hb = (t & 15) * 4;
    {
        float s[4];
#pragma unroll
        for (int x = 0; x < 4; x++) s[x] = sB[hb + x];
        for (int f = 0; f < NIN + MOUT; f++) {
            const float a = aug[nn * 80 + f];
#pragma unroll
            for (int x = 0; x < 4; x++) s[x] = fmaf(a, sW1[f * 64 + hb + x], s[x]);
        }
#pragma unroll
        for (int x = 0; x < 4; x++) h1[nn * 64 + hb + x] = fmaxf(s[x], 0.f);
    }
    __syncthreads();
    {
        float s[4];
#pragma unroll
        for (int x = 0; x < 4; x++) s[x] = sB[64 + hb + x];
        for (int f = 0; f < NHID; f++) {
            const float a = h1[nn * 64 + f];
#pragma unroll
            for (int x = 0; x < 4; x++) s[x] = fmaf(a, sW2[f * 64 + hb + x], s[x]);
        }
#pragma unroll
        for (int x = 0; x < 4; x++) h2[nn * 64 + hb + x] = fmaxf(s[x], 0.f);
    }
    __syncthreads();
    if ((t & 15) < 16) {
        const int o = t & 15;
        float s = sB[128 + o];
        for (int h = 0; h < NHID; h++)
            s = fmaf(h2[nn * 64 + h], sW3[h * 16 + o], s);
        out[(b * NOUT + o) * NN + (n0 + nn)] = s;
    }
}

// ---------------------------------------------------------------------------
extern "C" void kernel_launch(void* const* d_in, const int* in_sizes, int n_in,
                              void* d_out, int out_size)
{
    const float* inp       = (const float*)d_in[0];
    const float* rel_types = (const float*)d_in[3];
    const float* W1  = (const float*)d_in[4];
    const float* b1  = (const float*)d_in[5];
    const float* W2  = (const float*)d_in[6];
    const float* b2  = (const float*)d_in[7];
    const float* Wo1 = (const float*)d_in[8];
    const float* bo1 = (const float*)d_in[9];
    const float* Wo2 = (const float*)d_in[10];
    const float* bo2 = (const float*)d_in[11];
    const float* Wo3 = (const float*)d_in[12];
    const float* bo3 = (const float*)d_in[13];
    float* out = (float*)d_out;

    (void)cudaFuncSetAttribute(decoder_kernel,
                               cudaFuncAttributeMaxDynamicSharedMemorySize, DEC_DYN);
    (void)cudaFuncSetAttribute(node_kernel,
                               cudaFuncAttributeMaxDynamicSharedMemorySize, NODE_DYN);

    w2t_kernel<<<64, 256>>>(W2);
    uv_kernel<<<dim3(8, BB), 256>>>(inp, W1, b1);
    decoder_kernel<<<148, 512, DEC_DYN>>>(rel_types, W2, b2);
    node_kernel<<<256, 256, NODE_DYN>>>(inp, Wo1, bo1, Wo2, bo2, Wo3, bo3, out);
}

// round 7
// speedup vs baseline: 1.5330x; 1.5330x over previous
#include <cuda_runtime.h>
#include <cstdint>

#define BB 32
#define NN 128
#define NIN 16
#define MHID 64
#define MOUT 64
#define NHID 64
#define NOUT 16
#define KT 4
#define EDGES (NN * (NN - 1))

// Scratch (no cudaMalloc allowed)
__device__ float g_U[BB * NN * KT * MHID];   // [b][n][k][h] sender proj
__device__ float g_V[BB * NN * KT * MHID];   // [b][n][k][h] receiver proj + b1
__device__ float g_W2T[KT * MOUT * MHID];    // W2 transposed [k][m][kk], tf32-rounded
__device__ float g_AGG[BB * NN * MOUT];      // aggregated messages per node

// ---------------- helpers ----------------
__device__ __forceinline__ uint32_t smem_u32(const void* p) {
    uint32_t a;
    asm("{ .reg .u64 t; cvta.to.shared.u64 t, %1; cvt.u32.u64 %0, t; }" : "=r"(a) : "l"(p));
    return a;
}
__device__ __forceinline__ uint32_t f2tf32(float x) {
    uint32_t r; asm("cvt.rna.tf32.f32 %0, %1;" : "=r"(r) : "f"(x)); return r;
}

#if defined(__CUDA_ARCH_FEAT_SM103_ALL)
__device__ __forceinline__ void mma_tf32_ss(uint32_t d, uint64_t a, uint64_t b,
                                            uint32_t idesc, uint32_t en) {
    asm volatile(
        "{\n\t.reg .pred p;\n\tsetp.ne.u32 p, %4, 0;\n\t"
        "tcgen05.mma.cta_group::1.kind::tf32 [%0], %1, %2, %3, {%5, %5, %5, %5}, p;\n\t}\n"
        :: "r"(d), "l"(a), "l"(b), "r"(idesc), "r"(en), "r"(0u) : "memory");
}
#define MBAR_WAIT_PARITY(addr, ph) do {                                          \
    uint32_t _m = (addr), _p = (ph), _done;                                      \
    asm volatile("{\n\t.reg .pred p;\n\t"                                        \
        "mbarrier.try_wait.parity.acquire.cta.shared::cta.b64 p, [%1], %2;\n\t"  \
        "selp.b32 %0, 1, 0, p;\n\t}" : "=r"(_done) : "r"(_m), "r"(_p) : "memory");\
    if (!_done) {                                                                \
        asm volatile("{\n\t.reg .pred P1;\n\t"                                   \
            "WL_%=:\n\t"                                                         \
            "mbarrier.try_wait.parity.acquire.cta.shared::cta.b64 P1, [%0], %1, 0x989680;\n\t" \
            "@P1 bra.uni WD_%=;\n\tbra.uni WL_%=;\n\tWD_%=:\n\t}"                \
            :: "r"(_m), "r"(_p) : "memory");                                     \
    } } while (0)
#define LDTM_X32(r, addr)                                                        \
    asm volatile("tcgen05.ld.sync.aligned.32x32b.x32.b32 "                       \
        "{%0, %1, %2, %3, %4, %5, %6, %7, %8, %9, %10, %11, %12, %13, %14, %15," \
        " %16, %17, %18, %19, %20, %21, %22, %23, %24, %25, %26, %27, %28, %29, %30, %31}, [%32];" \
        : "=r"((r)[0]),  "=r"((r)[1]),  "=r"((r)[2]),  "=r"((r)[3]),             \
          "=r"((r)[4]),  "=r"((r)[5]),  "=r"((r)[6]),  "=r"((r)[7]),             \
          "=r"((r)[8]),  "=r"((r)[9]),  "=r"((r)[10]), "=r"((r)[11]),            \
          "=r"((r)[12]), "=r"((r)[13]), "=r"((r)[14]), "=r"((r)[15]),            \
          "=r"((r)[16]), "=r"((r)[17]), "=r"((r)[18]), "=r"((r)[19]),            \
          "=r"((r)[20]), "=r"((r)[21]), "=r"((r)[22]), "=r"((r)[23]),            \
          "=r"((r)[24]), "=r"((r)[25]), "=r"((r)[26]), "=r"((r)[27]),            \
          "=r"((r)[28]), "=r"((r)[29]), "=r"((r)[30]), "=r"((r)[31])             \
        : "r"(addr))
#define IDESC_TF32 0x08100910u
#define DESC_BASE ((2ull << 61) | (1ull << 46) | (64ull << 32) | (1ull << 16))
__device__ __forceinline__ uint64_t mk_desc(uint32_t addr) {
    return DESC_BASE | ((uint64_t)(addr >> 4) & 0x3FFF);
}
#endif

// decoder dynamic smem layout (from 1024-aligned base)
#define OFF_B     0          // 4 x 16384 = 65536 (W2T, SW128)
#define OFF_A     65536      // 4 x 32768 = 131072 (h1 tiles, SW128)
#define DEC_DYN   (65536 + 131072 + 1024)

// node-MLP kernel smem (float indices)
#define NOFF_W1   0          // 80*64
#define NOFF_W2   5120       // 64*64
#define NOFF_W3   9216       // 64*16
#define NOFF_B    10240      // 144
#define NOFF_AUG  10384      // 64*81
#define NOFF_H1   15568      // 64*65
#define NOFF_H2   19728      // 64*65
#define NODE_DYN  (23888 * 4)

// ---------------------------------------------------------------------------
// uv + fused w2t: grid (8, BB), 256 threads, 16 nodes per CTA.
// ---------------------------------------------------------------------------
__global__ __launch_bounds__(256) void uv_kernel(
    const float* __restrict__ inp, const float* __restrict__ W1,
    const float* __restrict__ b1, const float* __restrict__ W2)
{
    const int g = blockIdx.x, b = blockIdx.y;
    const int n0 = g * 16;
    const int t = threadIdx.x;
    const int k = t >> 6, h = t & 63;

    // fused w2t: blocks with b==0 transpose W2 -> g_W2T (tf32-rounded)
    if (b == 0) {
        for (int idx = g * 2048 + t; idx < (g + 1) * 2048; idx += 256) {
            const int kk2 = idx >> 12, rem = idx & 4095, kki = rem >> 6, m = rem & 63;
            ((uint32_t*)g_W2T)[(kk2 * MOUT + m) * MHID + kki] =
                f2tf32(W2[(kk2 * MHID + kki) * MOUT + m]);
        }
    }

    __shared__ float xs[16][NIN];
    {
        const int nn = t & 15, f = t >> 4;
        xs[nn][f] = inp[(b * NIN + f) * NN + n0 + nn];
    }
    __syncthreads();

    const float* w = W1 + k * (2 * NIN) * MHID;
    const float bv = b1[k * MHID + h];
    float u[16], v[16];
#pragma unroll
    for (int nn = 0; nn < 16; nn++) { u[nn] = 0.f; v[nn] = bv; }
#pragma unroll
    for (int f = 0; f < NIN; f++) {
        const float wu = w[f * MHID + h];
        const float wv = w[(NIN + f) * MHID + h];
#pragma unroll
        for (int nn = 0; nn < 16; nn++) {
            u[nn] = fmaf(xs[nn][f], wu, u[nn]);
            v[nn] = fmaf(xs[nn][f], wv, v[nn]);
        }
    }
#pragma unroll
    for (int nn = 0; nn < 16; nn++) {
        g_U[((b * NN + n0 + nn) * KT + k) * MHID + h] = u[nn];
        g_V[((b * NN + n0 + nn) * KT + k) * MHID + h] = v[nn];
    }
}

// ---------------------------------------------------------------------------
// Persistent decoder: grid 148, 512 threads. Lean per-tile pipeline.
// ---------------------------------------------------------------------------
__global__ __launch_bounds__(512, 1) void decoder_kernel(
    const float* __restrict__ rel_types, const float* __restrict__ W2,
    const float* __restrict__ b2)
{
    extern __shared__ char dsm[];
    __shared__ float b2s[KT][MOUT];
    __shared__ float part[16][MOUT];
    __shared__ uint32_t tmem_ptr_s;
    __shared__ __align__(8) uint64_t mbar;

    const int t = threadIdx.x;
    const int wid = t >> 5, lane = t & 31;

    const uint32_t dyn = smem_u32(dsm);
    const uint32_t base = (dyn + 1023) & ~1023u;
    char* P = dsm + (base - dyn);

    if (t < 256) b2s[t >> 6][t & 63] = b2[t];

#if defined(__CUDA_ARCH_FEAT_SM103_ALL)
    const uint32_t mb = smem_u32(&mbar);

    // stage 4 B tiles (W2T, SW128) once
    for (int idx = t; idx < KT * 64 * 16; idx += 512) {
        const int k = idx >> 10, n = (idx >> 4) & 63, c = (idx & 15) * 4;
        uint4 w4 = *(const uint4*)((const uint32_t*)g_W2T + (k * MOUT + n) * MHID + c);
        uint32_t byte = ((n >> 3) + (c >> 5) * 8) * 1024 + (n & 7) * 128 + (c & 31) * 4;
        byte ^= (byte >> 3) & 0x70;
        *(uint4*)(P + OFF_B + k * 16384 + byte) = w4;
    }
    if (t == 0)
        asm volatile("mbarrier.init.shared.b64 [%0], 1;" :: "r"(mb) : "memory");
    if (wid == 0) {
        asm volatile("tcgen05.alloc.cta_group::1.sync.aligned.shared::cta.b32 [%0], %1;"
                     :: "r"(smem_u32(&tmem_ptr_s)), "r"(512u) : "memory");
        asm volatile("tcgen05.relinquish_alloc_permit.cta_group::1.sync.aligned;");
    }
    __syncthreads();
    const uint32_t tmem = tmem_ptr_s;

    // build-thread constants: fixed (k, col-group, base row)
    const int bk = (t >> 4) & 3;     // k tile
    const int cg = t & 15;           // column group (4 cols)
    const int r0 = t >> 6;           // base row 0..7
    // incremental STS base: swizzle reduces to XOR of r0<<4 (constant per thread)
    char* sts0 = P + OFF_A + bk * 32768 + ((cg >= 8) ? 16384 : 0) + r0 * 128
               + (((cg & 7) ^ r0) << 4);
    const float* ubase = g_U + bk * 64 + cg * 4;   // + b*131072 + j*256

    // epilogue-warp constants
    const int kq = wid >> 2;                 // k bank
    const int jrow = (wid & 3) * 32 + lane;  // edge row (TMEM lane)

    int ph = 0, tc = 0, pq = 0, pb = 0, pi = 0;

    auto do_epilogue = [&](int eb, int ei, int eq, float prt) {
        asm volatile("tcgen05.fence::after_thread_sync;" ::: "memory");
        const uint32_t bankcol = tmem + (eq * 4 + kq) * 64;
#pragma unroll
        for (int chv = 0; chv < 2; chv++) {
            uint32_t d[32];
            LDTM_X32(d, bankcol + chv * 32);
            asm volatile("tcgen05.wait::ld.sync.aligned;" ::: "memory");
            float a[32];
#pragma unroll
            for (int c = 0; c < 32; c++)
                a[c] = prt * fmaxf(__uint_as_float(d[c]) + b2s[kq][chv * 32 + c], 0.f);
            // split-butterfly: lane L ends with col L of this 32-col chunk
#pragma unroll
            for (int o = 16; o >= 1; o >>= 1) {
                const bool up = (lane & o) != 0;
#pragma unroll
                for (int c = 0; c < 16; c++) {
                    if (c >= o) break;
                    const float send = up ? a[c] : a[c + o];
                    const float keep = up ? a[c + o] : a[c];
                    a[c] = keep + __shfl_xor_sync(0xFFFFFFFFu, send, o);
                }
            }
            part[wid][chv * 32 + lane] = a[0];
        }
        asm volatile("tcgen05.fence::before_thread_sync;" ::: "memory");
        __syncthreads();
        if (t < 64) {
            float s = 0.f;
#pragma unroll
            for (int w = 0; w < 16; w++) s += part[w][t];
            g_AGG[(eb * NN + ei) * MOUT + t] = s;
        }
    };

    for (int tile = blockIdx.x; tile < BB * NN; tile += gridDim.x, tc++) {
        const int b = tile >> 7, i = tile & 127;
        const int q = tc & 1;

        // prefetches (before the mbar wait, to hide L2 latency)
        const float4 vv = *(const float4*)(g_V + (b * NN + i) * (KT * MHID)
                                           + bk * MHID + cg * 4);
        float prt = 0.f;
        if (tc > 0 && jrow < NN - 1)
            prt = rel_types[((size_t)pb * EDGES + (size_t)pi * (NN - 1) + jrow) * KT + kq];

        if (tc > 0) { MBAR_WAIT_PARITY(mb, ph); ph ^= 1; }  // MMA(tc-1) done: A free

        // ---- build all 4 A tiles (incremental addressing) ----
        {
            const float* us = ubase + b * (NN * KT * MHID);
            char* sp = sts0;
#pragma unroll
            for (int it = 0; it < 16; it++, sp += 1024) {
                const int r = r0 + it * 8;
                uint4 w4 = make_uint4(0u, 0u, 0u, 0u);
                if (r < NN - 1) {
                    const int j = r + (r >= i);
                    const float4 u = *(const float4*)(us + j * (KT * MHID));
                    w4.x = f2tf32(fmaxf(u.x + vv.x, 0.f));
                    w4.y = f2tf32(fmaxf(u.y + vv.y, 0.f));
                    w4.z = f2tf32(fmaxf(u.z + vv.z, 0.f));
                    w4.w = f2tf32(fmaxf(u.w + vv.w, 0.f));
                }
                *(uint4*)sp = w4;
            }
        }
        __syncthreads();

        // ---- issue 4 GEMMs (32 dispatches) + 1 commit ----
        if (t == 0) {
            asm volatile("fence.proxy.async.shared::cta;" ::: "memory");
#pragma unroll
            for (int k = 0; k < KT; k++) {
                const uint64_t ad = mk_desc(base + OFF_A + k * 32768);
                const uint64_t bd = mk_desc(base + OFF_B + k * 16384);
                const uint32_t dcol = tmem + (q * 4 + k) * 64;
#pragma unroll
                for (int s = 0; s < 8; s++)
                    mma_tf32_ss(dcol,
                                ad + ((s >> 2) ? 1024u : 0u) + (s & 3) * 2,
                                bd + ((s >> 2) ? 512u : 0u) + (s & 3) * 2,
                                IDESC_TF32, (uint32_t)(s > 0));
            }
            asm volatile(
                "tcgen05.commit.cta_group::1.mbarrier::arrive::one.shared::cluster.b64 [%0];"
                :: "r"(mb) : "memory");
        }

        // ---- epilogue(tc-1) overlaps MMA(tc) ----
        if (tc > 0) do_epilogue(pb, pi, pq, prt);

        pb = b; pi = i; pq = q;
    }
    if (tc > 0) {
        float prt = 0.f;
        if (jrow < NN - 1)
            prt = rel_types[((size_t)pb * EDGES + (size_t)pi * (NN - 1) + jrow) * KT + kq];
        MBAR_WAIT_PARITY(mb, ph); ph ^= 1;
        do_epilogue(pb, pi, pq, prt);
    }

    __syncthreads();
    if (t == 0)
        asm volatile("mbarrier.inval.shared.b64 [%0];" :: "r"(mb) : "memory");
    if (wid == 0)
        asm volatile("tcgen05.dealloc.cta_group::1.sync.aligned.b32 %0, %1;"
                     :: "r"(tmem), "r"(512u));
#else
    // ============ SIMT fallback (compile-only for plain sm_103) ============
    __shared__ float vs0[KT][MHID];
    __shared__ float rts0[NN][KT];
    float* h1  = (float*)P;                  // [128][68]
    float* W2s = (float*)(P + 128 * 68 * 4); // [64][64]

    for (int tile = blockIdx.x; tile < BB * NN; tile += gridDim.x) {
        const int b = tile >> 7, i = tile & 127;
        __syncthreads();
        if (t < 256) vs0[t >> 6][t & 63] = g_V[((b * NN + i) * KT) * MHID + t];
        {
            const float* rtp = rel_types + (size_t)(b * EDGES + i * (NN - 1)) * KT;
            for (int idx = t; idx < (NN - 1) * KT; idx += 512)
                rts0[idx >> 2][idx & 3] = rtp[idx];
            if (t < KT) rts0[NN - 1][t] = 0.f;
        }
        const int r = t >> 2, cq = (t & 3) * 16;
        float aggv[16];
#pragma unroll
        for (int c = 0; c < 16; c++) aggv[c] = 0.f;
        for (int k = 0; k < KT; k++) {
            __syncthreads();
            for (int idx = t; idx < 128 * 64; idx += 512) {
                const int rr = idx >> 6, h = idx & 63;
                float val = 0.f;
                if (rr < NN - 1) {
                    const int j = rr + (rr >= i);
                    val = fmaxf(g_U[((b * NN + j) * KT + k) * MHID + h] + vs0[k][h], 0.f);
                }
                h1[rr * 68 + h] = val;
            }
            for (int idx = t; idx < 64 * 64; idx += 512)
                W2s[idx] = W2[k * 64 * 64 + idx];
            __syncthreads();
            float acc[16];
#pragma unroll
            for (int c = 0; c < 16; c++) acc[c] = 0.f;
            for (int kk = 0; kk < 64; kk++) {
                const float a = h1[r * 68 + kk];
#pragma unroll
                for (int c = 0; c < 16; c++)
                    acc[c] = fmaf(a, W2s[kk * 64 + cq + c], acc[c]);
            }
            const float rt = rts0[r][k];
#pragma unroll
            for (int c = 0; c < 16; c++)
                aggv[c] = fmaf(rt, fmaxf(acc[c] + b2s[k][cq + c], 0.f), aggv[c]);
        }
        __syncthreads();
        float* red = (float*)P;
#pragma unroll
        for (int c = 0; c < 16; c++) red[(cq + c) * 132 + r] = aggv[c];
        __syncthreads();
        if (t < 64) {
            float s = 0.f;
            for (int l = 0; l < 128; l++) s += red[t * 132 + l];
            g_AGG[(b * NN + i) * MOUT + t] = s;
        }
        __syncthreads();
    }
#endif
}

// ---------------------------------------------------------------------------
// Node MLP: grid 64 (64 nodes/CTA), 256 threads, weights staged once.
// ---------------------------------------------------------------------------
__global__ __launch_bounds__(256) void node_kernel(
    const float* __restrict__ inp,
    const float* __restrict__ Wo1, const float* __restrict__ bo1,
    const float* __restrict__ Wo2, const float* __restrict__ bo2,
    const float* __restrict__ Wo3, const float* __restrict__ bo3,
    float* __restrict__ out)
{
    extern __shared__ float nsm[];
    float* sW1 = nsm + NOFF_W1;
    float* sW2 = nsm + NOFF_W2;
    float* sW3 = nsm + NOFF_W3;
    float* sB  = nsm + NOFF_B;
    float* aug = nsm + NOFF_AUG;   // [64][81]
    float* h1  = nsm + NOFF_H1;    // [64][65]
    float* h2  = nsm + NOFF_H2;    // [64][65]

    const int t = threadIdx.x;
    const int b = blockIdx.x >> 1, n0 = (blockIdx.x & 1) * 64;

    for (int idx = t; idx < 80 * 64; idx += 256) sW1[idx] = Wo1[idx];
    for (int idx = t; idx < 64 * 64; idx += 256) sW2[idx] = Wo2[idx];
    for (int idx = t; idx < 64 * 16; idx += 256) sW3[idx] = Wo3[idx];
    if (t < 64) sB[t] = bo1[t];
    if (t < 64) sB[64 + t] = bo2[t];
    if (t < 16) sB[128 + t] = bo3[t];

    {   // aug fill: thread (nn = t>>2, f block of 20)
        const int nn = t >> 2, f0 = (t & 3) * 20;
#pragma unroll
        for (int f = f0; f < f0 + 20; f++) {
            aug[nn * 81 + f] = (f < NIN)
                ? inp[(b * NIN + f) * NN + (n0 + nn)]
                : g_AGG[(b * NN + n0 + nn) * MOUT + (f - NIN)];
        }
    }
    __syncthreads();

    const int nn = t & 63, s = t >> 6;     // 4 threads per node
    {
        float acc[16];
#pragma unroll
        for (int x = 0; x < 16; x++) acc[x] = sB[s * 16 + x];
        for (int f = 0; f < NIN + MOUT; f++) {
            const float a = aug[nn * 81 + f];
#pragma unroll
            for (int x = 0; x < 16; x++)
                acc[x] = fmaf(a, sW1[f * 64 + s * 16 + x], acc[x]);
        }
#pragma unroll
        for (int x = 0; x < 16; x++) h1[nn * 65 + s * 16 + x] = fmaxf(acc[x], 0.f);
    }
    __syncthreads();
    {
        float acc[16];
#pragma unroll
        for (int x = 0; x < 16; x++) acc[x] = sB[64 + s * 16 + x];
        for (int f = 0; f < NHID; f++) {
            const float a = h1[nn * 65 + f];
#pragma unroll
            for (int x = 0; x < 16; x++)
                acc[x] = fmaf(a, sW2[f * 64 + s * 16 + x], acc[x]);
        }
#pragma unroll
        for (int x = 0; x < 16; x++) h2[nn * 65 + s * 16 + x] = fmaxf(acc[x], 0.f);
    }
    __syncthreads();
    {
        float acc[4];
#pragma unroll
        for (int x = 0; x < 4; x++) acc[x] = sB[128 + s * 4 + x];
        for (int f = 0; f < NHID; f++) {
            const float a = h2[nn * 65 + f];
#pragma unroll
            for (int x = 0; x < 4; x++)
                acc[x] = fmaf(a, sW3[f * 16 + s * 4 + x], acc[x]);
        }
#pragma unroll
        for (int x = 0; x < 4; x++)
            out[(b * NOUT + s * 4 + x) * NN + (n0 + nn)] = acc[x];
    }
}

// ---------------------------------------------------------------------------
extern "C" void kernel_launch(void* const* d_in, const int* in_sizes, int n_in,
                              void* d_out, int out_size)
{
    const float* inp       = (const float*)d_in[0];
    const float* rel_types = (const float*)d_in[3];
    const float* W1  = (const float*)d_in[4];
    const float* b1  = (const float*)d_in[5];
    const float* W2  = (const float*)d_in[6];
    const float* b2  = (const float*)d_in[7];
    const float* Wo1 = (const float*)d_in[8];
    const float* bo1 = (const float*)d_in[9];
    const float* Wo2 = (const float*)d_in[10];
    const float* bo2 = (const float*)d_in[11];
    const float* Wo3 = (const float*)d_in[12];
    const float* bo3 = (const float*)d_in[13];
    float* out = (float*)d_out;

    (void)cudaFuncSetAttribute(decoder_kernel,
                               cudaFuncAttributeMaxDynamicSharedMemorySize, DEC_DYN);
    (void)cudaFuncSetAttribute(node_kernel,
                               cudaFuncAttributeMaxDynamicSharedMemorySize, NODE_DYN);

    uv_kernel<<<dim3(8, BB), 256>>>(inp, W1, b1, W2);
    decoder_kernel<<<148, 512, DEC_DYN>>>(rel_types, W2, b2);
    node_kernel<<<64, 256, NODE_DYN>>>(inp, Wo1, bo1, Wo2, bo2, Wo3, bo3, out);
}

// round 8
// speedup vs baseline: 1.6802x; 1.0960x over previous
#include <cuda_runtime.h>
#include <cstdint>

#define BB 32
#define NN 128
#define NIN 16
#define MHID 64
#define MOUT 64
#define NHID 64
#define NOUT 16
#define KT 4
#define EDGES (NN * (NN - 1))

// Scratch (no cudaMalloc allowed)
__device__ float g_U[BB * NN * KT * MHID];   // [b][n][k][h] sender proj
__device__ float g_V[BB * NN * KT * MHID];   // [b][n][k][h] receiver proj + b1
__device__ float g_W2T[KT * MOUT * MHID];    // W2 transposed [k][m][kk], tf32-rounded
__device__ float g_AGG[BB * NN * MOUT];      // aggregated messages per node

// ---------------- helpers ----------------
__device__ __forceinline__ uint32_t smem_u32(const void* p) {
    uint32_t a;
    asm("{ .reg .u64 t; cvta.to.shared.u64 t, %1; cvt.u32.u64 %0, t; }" : "=r"(a) : "l"(p));
    return a;
}
__device__ __forceinline__ uint32_t f2tf32(float x) {
    uint32_t r; asm("cvt.rna.tf32.f32 %0, %1;" : "=r"(r) : "f"(x)); return r;
}

#if defined(__CUDA_ARCH_FEAT_SM103_ALL)
__device__ __forceinline__ void mma_tf32_ss(uint32_t d, uint64_t a, uint64_t b,
                                            uint32_t idesc, uint32_t en) {
    asm volatile(
        "{\n\t.reg .pred p;\n\tsetp.ne.u32 p, %4, 0;\n\t"
        "tcgen05.mma.cta_group::1.kind::tf32 [%0], %1, %2, %3, {%5, %5, %5, %5}, p;\n\t}\n"
        :: "r"(d), "l"(a), "l"(b), "r"(idesc), "r"(en), "r"(0u) : "memory");
}
#define MBAR_WAIT_PARITY(addr, ph) do {                                          \
    uint32_t _m = (addr), _p = (ph), _done;                                      \
    asm volatile("{\n\t.reg .pred p;\n\t"                                        \
        "mbarrier.try_wait.parity.acquire.cta.shared::cta.b64 p, [%1], %2;\n\t"  \
        "selp.b32 %0, 1, 0, p;\n\t}" : "=r"(_done) : "r"(_m), "r"(_p) : "memory");\
    if (!_done) {                                                                \
        asm volatile("{\n\t.reg .pred P1;\n\t"                                   \
            "WL_%=:\n\t"                                                         \
            "mbarrier.try_wait.parity.acquire.cta.shared::cta.b64 P1, [%0], %1, 0x989680;\n\t" \
            "@P1 bra.uni WD_%=;\n\tbra.uni WL_%=;\n\tWD_%=:\n\t}"                \
            :: "r"(_m), "r"(_p) : "memory");                                     \
    } } while (0)
#define LDTM_X32(r, addr)                                                        \
    asm volatile("tcgen05.ld.sync.aligned.32x32b.x32.b32 "                       \
        "{%0, %1, %2, %3, %4, %5, %6, %7, %8, %9, %10, %11, %12, %13, %14, %15," \
        " %16, %17, %18, %19, %20, %21, %22, %23, %24, %25, %26, %27, %28, %29, %30, %31}, [%32];" \
        : "=r"((r)[0]),  "=r"((r)[1]),  "=r"((r)[2]),  "=r"((r)[3]),             \
          "=r"((r)[4]),  "=r"((r)[5]),  "=r"((r)[6]),  "=r"((r)[7]),             \
          "=r"((r)[8]),  "=r"((r)[9]),  "=r"((r)[10]), "=r"((r)[11]),            \
          "=r"((r)[12]), "=r"((r)[13]), "=r"((r)[14]), "=r"((r)[15]),            \
          "=r"((r)[16]), "=r"((r)[17]), "=r"((r)[18]), "=r"((r)[19]),            \
          "=r"((r)[20]), "=r"((r)[21]), "=r"((r)[22]), "=r"((r)[23]),            \
          "=r"((r)[24]), "=r"((r)[25]), "=r"((r)[26]), "=r"((r)[27]),            \
          "=r"((r)[28]), "=r"((r)[29]), "=r"((r)[30]), "=r"((r)[31])             \
        : "r"(addr))
#define IDESC_TF32 0x08100910u
#define DESC_BASE ((2ull << 61) | (1ull << 46) | (64ull << 32) | (1ull << 16))
__device__ __forceinline__ uint64_t mk_desc(uint32_t addr) {
    return DESC_BASE | ((uint64_t)(addr >> 4) & 0x3FFF);
}
#endif

// decoder dynamic smem layout (from 1024-aligned base)
#define OFF_B     0          // 4 x 16384 = 65536 (W2T, SW128)
#define OFF_A     65536      // 4 x 32768 = 131072 (h1 tiles, SW128)
#define DEC_DYN   (65536 + 131072 + 1024)

// node-MLP kernel smem (float indices)
#define NOFF_W1   0
#define NOFF_W2   5120
#define NOFF_W3   9216
#define NOFF_B    10240
#define NOFF_AUG  10384      // 64*81
#define NOFF_H1   15568      // 64*65
#define NOFF_H2   19728      // 64*65
#define NODE_DYN  (23888 * 4)

// ---------------------------------------------------------------------------
// uv + fused w2t: grid (8, BB), 256 threads, 16 nodes per CTA.
// ---------------------------------------------------------------------------
__global__ __launch_bounds__(256) void uv_kernel(
    const float* __restrict__ inp, const float* __restrict__ W1,
    const float* __restrict__ b1, const float* __restrict__ W2)
{
    const int g = blockIdx.x, b = blockIdx.y;
    const int n0 = g * 16;
    const int t = threadIdx.x;
    const int k = t >> 6, h = t & 63;

    if (b == 0) {
        for (int idx = g * 2048 + t; idx < (g + 1) * 2048; idx += 256) {
            const int kk2 = idx >> 12, rem = idx & 4095, kki = rem >> 6, m = rem & 63;
            ((uint32_t*)g_W2T)[(kk2 * MOUT + m) * MHID + kki] =
                f2tf32(W2[(kk2 * MHID + kki) * MOUT + m]);
        }
    }

    __shared__ float xs[16][NIN];
    {
        const int nn = t & 15, f = t >> 4;
        xs[nn][f] = inp[(b * NIN + f) * NN + n0 + nn];
    }
    __syncthreads();

    const float* w = W1 + k * (2 * NIN) * MHID;
    const float bv = b1[k * MHID + h];
    float u[16], v[16];
#pragma unroll
    for (int nn = 0; nn < 16; nn++) { u[nn] = 0.f; v[nn] = bv; }
#pragma unroll
    for (int f = 0; f < NIN; f++) {
        const float wu = w[f * MHID + h];
        const float wv = w[(NIN + f) * MHID + h];
#pragma unroll
        for (int nn = 0; nn < 16; nn++) {
            u[nn] = fmaf(xs[nn][f], wu, u[nn]);
            v[nn] = fmaf(xs[nn][f], wv, v[nn]);
        }
    }
#pragma unroll
    for (int nn = 0; nn < 16; nn++) {
        g_U[((b * NN + n0 + nn) * KT + k) * MHID + h] = u[nn];
        g_V[((b * NN + n0 + nn) * KT + k) * MHID + h] = v[nn];
    }
}

// ---------------------------------------------------------------------------
// Persistent warp-specialized decoder: grid 148, 512 threads.
//   warps 0-7  (t 0..255)   : A-build + MMA issue
//   warps 8-15 (t 256..511) : TMEM epilogue + aggregation
// ---------------------------------------------------------------------------
__global__ __launch_bounds__(512, 1) void decoder_kernel(
    const float* __restrict__ rel_types, const float* __restrict__ W2,
    const float* __restrict__ b2)
{
    extern __shared__ char dsm[];
    __shared__ float b2s[KT][MOUT];
    __shared__ float part[8][MOUT];
    __shared__ uint32_t tmem_ptr_s;
    __shared__ __align__(8) uint64_t mbar[3];  // [0]=mma done, [1]=free bank0, [2]=free bank1

    const int t = threadIdx.x;
    const int wid = t >> 5, lane = t & 31;

    const uint32_t dyn = smem_u32(dsm);
    const uint32_t base = (dyn + 1023) & ~1023u;
    char* P = dsm + (base - dyn);

    if (t < 256) b2s[t >> 6][t & 63] = b2[t];

#if defined(__CUDA_ARCH_FEAT_SM103_ALL)
    const uint32_t mb_mma   = smem_u32(&mbar[0]);
    const uint32_t mb_free0 = smem_u32(&mbar[1]);
    const uint32_t mb_free1 = smem_u32(&mbar[2]);

    // stage 4 B tiles (W2T, SW128) once
    for (int idx = t; idx < KT * 64 * 16; idx += 512) {
        const int k = idx >> 10, n = (idx >> 4) & 63, c = (idx & 15) * 4;
        uint4 w4 = *(const uint4*)((const uint32_t*)g_W2T + (k * MOUT + n) * MHID + c);
        uint32_t byte = ((n >> 3) + (c >> 5) * 8) * 1024 + (n & 7) * 128 + (c & 31) * 4;
        byte ^= (byte >> 3) & 0x70;
        *(uint4*)(P + OFF_B + k * 16384 + byte) = w4;
    }
    if (t == 0) {
        asm volatile("mbarrier.init.shared.b64 [%0], 1;" :: "r"(mb_mma) : "memory");
        asm volatile("mbarrier.init.shared.b64 [%0], 1;" :: "r"(mb_free0) : "memory");
        asm volatile("mbarrier.init.shared.b64 [%0], 1;" :: "r"(mb_free1) : "memory");
    }
    if (wid == 0) {
        asm volatile("tcgen05.alloc.cta_group::1.sync.aligned.shared::cta.b32 [%0], %1;"
                     :: "r"(smem_u32(&tmem_ptr_s)), "r"(512u) : "memory");
        asm volatile("tcgen05.relinquish_alloc_permit.cta_group::1.sync.aligned;");
    }
    __syncthreads();
    const uint32_t tmem = tmem_ptr_s;

    if (wid < 8) {
        // ========================= BUILDERS =========================
        // thread constants: fixed (k tile, col group, rows r0 / r0+4 mod 8)
        const int bk = (t >> 4) & 3;
        const int cg = t & 15;
        const int r0 = t >> 6;              // 0..3
        char* Abk = P + OFF_A + bk * 32768 + ((cg >= 8) ? 16384 : 0);
        char* sts0 = Abk + r0 * 128 + (((cg & 7) ^ r0) << 4);
        char* sts1 = Abk + (r0 + 4) * 128 + (((cg & 7) ^ (r0 + 4)) << 4);
        const float* ubase = g_U + bk * 64 + cg * 4;
        const float* vbase = g_V + bk * MHID + cg * 4;

        int phB = 0, phF0 = 0, phF1 = 0, tc = 0;
        for (int tile = blockIdx.x; tile < BB * NN; tile += gridDim.x, tc++) {
            const int b = tile >> 7, i = tile & 127;
            const int q = tc & 1;

            const float4 vv = *(const float4*)(vbase + (b * NN + i) * (KT * MHID));
            if (tc > 0) { MBAR_WAIT_PARITY(mb_mma, phB); phB ^= 1; }  // A free

            {
                const float* us = ubase + b * (NN * KT * MHID);
                char* p0 = sts0;
                char* p1 = sts1;
#pragma unroll
                for (int it = 0; it < 16; it++, p0 += 1024, p1 += 1024) {
                    const int ra = r0 + it * 8;
                    const int rb = ra + 4;
                    uint4 wa = make_uint4(0u, 0u, 0u, 0u);
                    uint4 wb = make_uint4(0u, 0u, 0u, 0u);
                    {
                        const int j = ra + (ra >= i);
                        const float4 u = *(const float4*)(us + j * (KT * MHID));
                        wa.x = f2tf32(fmaxf(u.x + vv.x, 0.f));
                        wa.y = f2tf32(fmaxf(u.y + vv.y, 0.f));
                        wa.z = f2tf32(fmaxf(u.z + vv.z, 0.f));
                        wa.w = f2tf32(fmaxf(u.w + vv.w, 0.f));
                    }
                    if (rb < NN - 1 || (rb == NN - 1 && false)) {}
                    if (rb < NN - 1) {
                        const int j = rb + (rb >= i);
                        const float4 u = *(const float4*)(us + j * (KT * MHID));
                        wb.x = f2tf32(fmaxf(u.x + vv.x, 0.f));
                        wb.y = f2tf32(fmaxf(u.y + vv.y, 0.f));
                        wb.z = f2tf32(fmaxf(u.z + vv.z, 0.f));
                        wb.w = f2tf32(fmaxf(u.w + vv.w, 0.f));
                    }
                    *(uint4*)p0 = wa;
                    *(uint4*)p1 = wb;
                }
            }
            asm volatile("bar.sync 1, 256;" ::: "memory");

            if (t == 0) {
                if (tc >= 2) {
                    if (q == 0) { MBAR_WAIT_PARITY(mb_free0, phF0); phF0 ^= 1; }
                    else        { MBAR_WAIT_PARITY(mb_free1, phF1); phF1 ^= 1; }
                }
                asm volatile("fence.proxy.async.shared::cta;" ::: "memory");
#pragma unroll
                for (int k = 0; k < KT; k++) {
                    const uint64_t ad = mk_desc(base + OFF_A + k * 32768);
                    const uint64_t bd = mk_desc(base + OFF_B + k * 16384);
                    const uint32_t dcol = tmem + (q * 4 + k) * 64;
#pragma unroll
                    for (int s = 0; s < 8; s++)
                        mma_tf32_ss(dcol,
                                    ad + ((s >> 2) ? 1024u : 0u) + (s & 3) * 2,
                                    bd + ((s >> 2) ? 512u : 0u) + (s & 3) * 2,
                                    IDESC_TF32, (uint32_t)(s > 0));
                }
                asm volatile(
                    "tcgen05.commit.cta_group::1.mbarrier::arrive::one.shared::cluster.b64 [%0];"
                    :: "r"(mb_mma) : "memory");
            }
        }
    } else {
        // ========================= EPILOGUE =========================
        const int sub = wid & 3;               // TMEM subpartition
        const int kp = (wid >> 2) & 1;         // k pair: {2kp, 2kp+1}
        const int jrow = sub * 32 + lane;
        const int ewid = wid - 8;

        int phE = 0, tc = 0;
        for (int tile = blockIdx.x; tile < BB * NN; tile += gridDim.x, tc++) {
            const int b = tile >> 7, i = tile & 127;
            const int q = tc & 1;

            float2 rt2 = make_float2(0.f, 0.f);
            if (jrow < NN - 1)
                rt2 = *(const float2*)(rel_types +
                        ((size_t)b * EDGES + (size_t)i * (NN - 1) + jrow) * KT + 2 * kp);

            MBAR_WAIT_PARITY(mb_mma, phE); phE ^= 1;   // MMA(tc) done
            asm volatile("tcgen05.fence::after_thread_sync;" ::: "memory");

#pragma unroll
            for (int chv = 0; chv < 2; chv++) {
                uint32_t d0[32], d1[32];
                LDTM_X32(d0, tmem + (q * 4 + 2 * kp) * 64 + chv * 32);
                LDTM_X32(d1, tmem + (q * 4 + 2 * kp + 1) * 64 + chv * 32);
                asm volatile("tcgen05.wait::ld.sync.aligned;" ::: "memory");
                float a[32];
#pragma unroll
                for (int c = 0; c < 32; c++) {
                    const float v0 = fmaxf(__uint_as_float(d0[c]) + b2s[2 * kp][chv * 32 + c], 0.f);
                    const float v1 = fmaxf(__uint_as_float(d1[c]) + b2s[2 * kp + 1][chv * 32 + c], 0.f);
                    a[c] = rt2.x * v0 + rt2.y * v1;
                }
                // split-butterfly: lane L ends with col L of this 32-col chunk
#pragma unroll
                for (int o = 16; o >= 1; o >>= 1) {
                    const bool up = (lane & o) != 0;
#pragma unroll
                    for (int c = 0; c < 16; c++) {
                        if (c >= o) break;
                        const float send = up ? a[c] : a[c + o];
                        const float keep = up ? a[c + o] : a[c];
                        a[c] = keep + __shfl_xor_sync(0xFFFFFFFFu, send, o);
                    }
                }
                part[ewid][chv * 32 + lane] = a[0];
            }
            asm volatile("tcgen05.fence::before_thread_sync;" ::: "memory");
            asm volatile("bar.sync 2, 256;" ::: "memory");
            if (t == 256) {   // TMEM bank-set q free
                if (q == 0)
                    asm volatile("mbarrier.arrive.shared.b64 _, [%0];" :: "r"(mb_free0) : "memory");
                else
                    asm volatile("mbarrier.arrive.shared.b64 _, [%0];" :: "r"(mb_free1) : "memory");
            }
            {
                const int m = t - 256;
                if (m < 64) {
                    float s = part[0][m];
#pragma unroll
                    for (int w = 1; w < 8; w++) s += part[w][m];
                    g_AGG[(b * NN + i) * MOUT + m] = s;
                }
            }
            asm volatile("bar.sync 2, 256;" ::: "memory");
        }
    }

    __syncthreads();
    if (t == 0) {
        asm volatile("mbarrier.inval.shared.b64 [%0];" :: "r"(mb_mma) : "memory");
        asm volatile("mbarrier.inval.shared.b64 [%0];" :: "r"(mb_free0) : "memory");
        asm volatile("mbarrier.inval.shared.b64 [%0];" :: "r"(mb_free1) : "memory");
    }
    if (wid == 0)
        asm volatile("tcgen05.dealloc.cta_group::1.sync.aligned.b32 %0, %1;"
                     :: "r"(tmem), "r"(512u));
#else
    // ============ SIMT fallback (compile-only for plain sm_103) ============
    __shared__ float vs0[KT][MHID];
    __shared__ float rts0[NN][KT];
    float* h1  = (float*)P;
    float* W2s = (float*)(P + 128 * 68 * 4);

    for (int tile = blockIdx.x; tile < BB * NN; tile += gridDim.x) {
        const int b = tile >> 7, i = tile & 127;
        __syncthreads();
        if (t < 256) vs0[t >> 6][t & 63] = g_V[((b * NN + i) * KT) * MHID + t];
        {
            const float* rtp = rel_types + (size_t)(b * EDGES + i * (NN - 1)) * KT;
            for (int idx = t; idx < (NN - 1) * KT; idx += 512)
                rts0[idx >> 2][idx & 3] = rtp[idx];
            if (t < KT) rts0[NN - 1][t] = 0.f;
        }
        const int r = t >> 2, cq = (t & 3) * 16;
        float aggv[16];
#pragma unroll
        for (int c = 0; c < 16; c++) aggv[c] = 0.f;
        for (int k = 0; k < KT; k++) {
            __syncthreads();
            for (int idx = t; idx < 128 * 64; idx += 512) {
                const int rr = idx >> 6, h = idx & 63;
                float val = 0.f;
                if (rr < NN - 1) {
                    const int j = rr + (rr >= i);
                    val = fmaxf(g_U[((b * NN + j) * KT + k) * MHID + h] + vs0[k][h], 0.f);
                }
                h1[rr * 68 + h] = val;
            }
            for (int idx = t; idx < 64 * 64; idx += 512)
                W2s[idx] = W2[k * 64 * 64 + idx];
            __syncthreads();
            float acc[16];
#pragma unroll
            for (int c = 0; c < 16; c++) acc[c] = 0.f;
            for (int kk = 0; kk < 64; kk++) {
                const float a = h1[r * 68 + kk];
#pragma unroll
                for (int c = 0; c < 16; c++)
                    acc[c] = fmaf(a, W2s[kk * 64 + cq + c], acc[c]);
            }
            const float rt = rts0[r][k];
#pragma unroll
            for (int c = 0; c < 16; c++)
                aggv[c] = fmaf(rt, fmaxf(acc[c] + b2s[k][cq + c], 0.f), aggv[c]);
        }
        __syncthreads();
        float* red = (float*)P;
#pragma unroll
        for (int c = 0; c < 16; c++) red[(cq + c) * 132 + r] = aggv[c];
        __syncthreads();
        if (t < 64) {
            float s = 0.f;
            for (int l = 0; l < 128; l++) s += red[t * 132 + l];
            g_AGG[(b * NN + i) * MOUT + t] = s;
        }
        __syncthreads();
    }
#endif
}

// ---------------------------------------------------------------------------
// Node MLP: grid 64 (64 nodes/CTA), 256 threads, weights staged once.
// ---------------------------------------------------------------------------
__global__ __launch_bounds__(256) void node_kernel(
    const float* __restrict__ inp,
    const float* __restrict__ Wo1, const float* __restrict__ bo1,
    const float* __restrict__ Wo2, const float* __restrict__ bo2,
    const float* __restrict__ Wo3, const float* __restrict__ bo3,
    float* __restrict__ out)
{
    extern __shared__ float nsm[];
    float* sW1 = nsm + NOFF_W1;
    float* sW2 = nsm + NOFF_W2;
    float* sW3 = nsm + NOFF_W3;
    float* sB  = nsm + NOFF_B;
    float* aug = nsm + NOFF_AUG;   // [64][81]
    float* h1  = nsm + NOFF_H1;    // [64][65]
    float* h2  = nsm + NOFF_H2;    // [64][65]

    const int t = threadIdx.x;
    const int b = blockIdx.x >> 1, n0 = (blockIdx.x & 1) * 64;

    for (int idx = t; idx < 80 * 64; idx += 256) sW1[idx] = Wo1[idx];
    for (int idx = t; idx < 64 * 64; idx += 256) sW2[idx] = Wo2[idx];
    for (int idx = t; idx < 64 * 16; idx += 256) sW3[idx] = Wo3[idx];
    if (t < 64) sB[t] = bo1[t];
    if (t < 64) sB[64 + t] = bo2[t];
    if (t < 16) sB[128 + t] = bo3[t];

    {
        const int nn = t >> 2, f0 = (t & 3) * 20;
#pragma unroll
        for (int f = f0; f < f0 + 20; f++) {
            aug[nn * 81 + f] = (f < NIN)
                ? inp[(b * NIN + f) * NN + (n0 + nn)]
                : g_AGG[(b * NN + n0 + nn) * MOUT + (f - NIN)];
        }
    }
    __syncthreads();

    const int nn = t & 63, s = t >> 6;
    {
        float acc[16];
#pragma unroll
        for (int x = 0; x < 16; x++) acc[x] = sB[s * 16 + x];
        for (int f = 0; f < NIN + MOUT; f++) {
            const float a = aug[nn * 81 + f];
#pragma unroll
            for (int x = 0; x < 16; x++)
                acc[x] = fmaf(a, sW1[f * 64 + s * 16 + x], acc[x]);
        }
#pragma unroll
        for (int x = 0; x < 16; x++) h1[nn * 65 + s * 16 + x] = fmaxf(acc[x], 0.f);
    }
    __syncthreads();
    {
        float acc[16];
#pragma unroll
        for (int x = 0; x < 16; x++) acc[x] = sB[64 + s * 16 + x];
        for (int f = 0; f < NHID; f++) {
            const float a = h1[nn * 65 + f];
#pragma unroll
            for (int x = 0; x < 16; x++)
                acc[x] = fmaf(a, sW2[f * 64 + s * 16 + x], acc[x]);
        }
#pragma unroll
        for (int x = 0; x < 16; x++) h2[nn * 65 + s * 16 + x] = fmaxf(acc[x], 0.f);
    }
    __syncthreads();
    {
        float acc[4];
#pragma unroll
        for (int x = 0; x < 4; x++) acc[x] = sB[128 + s * 4 + x];
        for (int f = 0; f < NHID; f++) {
            const float a = h2[nn * 65 + f];
#pragma unroll
            for (int x = 0; x < 4; x++)
                acc[x] = fmaf(a, sW3[f * 16 + s * 4 + x], acc[x]);
        }
#pragma unroll
        for (int x = 0; x < 4; x++)
            out[(b * NOUT + s * 4 + x) * NN + (n0 + nn)] = acc[x];
    }
}

// ---------------------------------------------------------------------------
extern "C" void kernel_launch(void* const* d_in, const int* in_sizes, int n_in,
                              void* d_out, int out_size)
{
    const float* inp       = (const float*)d_in[0];
    const float* rel_types = (const float*)d_in[3];
    const float* W1  = (const float*)d_in[4];
    const float* b1  = (const float*)d_in[5];
    const float* W2  = (const float*)d_in[6];
    const float* b2  = (const float*)d_in[7];
    const float* Wo1 = (const float*)d_in[8];
    const float* bo1 = (const float*)d_in[9];
    const float* Wo2 = (const float*)d_in[10];
    const float* bo2 = (const float*)d_in[11];
    const float* Wo3 = (const float*)d_in[12];
    const float* bo3 = (const float*)d_in[13];
    float* out = (float*)d_out;

    (void)cudaFuncSetAttribute(decoder_kernel,
                               cudaFuncAttributeMaxDynamicSharedMemorySize, DEC_DYN);
    (void)cudaFuncSetAttribute(node_kernel,
                               cudaFuncAttributeMaxDynamicSharedMemorySize, NODE_DYN);

    uv_kernel<<<dim3(8, BB), 256>>>(inp, W1, b1, W2);
    decoder_kernel<<<148, 512, DEC_DYN>>>(rel_types, W2, b2);
    node_kernel<<<64, 256, NODE_DYN>>>(inp, Wo1, bo1, Wo2, bo2, Wo3, bo3, out);
}